// round 4
// baseline (speedup 1.0000x reference)
#include <cuda_runtime.h>
#include <cuda_fp16.h>
#include <cstdint>

// ---------------------------------------------------------------------------
// DSDMSR multi-scale SRCNN cascade.
// conv1 (9x9,1->64) fp32 -> fp16 out; conv2 (5x5,64->32) fp16 mma.sync m16n8k16;
// conv3 (5x5,32->1) fp32.
// ---------------------------------------------------------------------------

__device__ __half g_t1h[134217728];          // conv1 out, [z][H][W][64] fp16 (256MB)
__device__ float  g_t2[67108864];            // conv2 out, [z][32][H][W] fp32 (256MB)
__device__ float  g_msf[2 * 1024 * 1024];
__device__ float  g_w1t[17 * 81 * 64];       // [u][tap][oc] fp32
__device__ __half g_w2h[17 * 4 * 25 * 2 * 32 * 8];  // fragment-major fp16

// ---------------------------------------------------------------------------
// Weight prep.
// w2 fragment-major: [u][ic-chunk(4)][tap(25)][m-tile(2)][lane(32)][8 halves]
// lane l: g=l>>2, t=l&3; halves order = {A[g][2t],A[g][2t+1],A[g+8][2t],
//   A[g+8][2t+1],A[g][2t+8],A[g][2t+9],A[g+8][2t+8],A[g+8][2t+9]}
// where A row = oc (m*16+...), col = ic within 16-chunk.
// ---------------------------------------------------------------------------
__global__ void prep_weights_kernel(const float* __restrict__ w1,
                                    const float* __restrict__ w2) {
    int idx = blockIdx.x * 256 + threadIdx.x;
    if (idx < 17 * 81 * 64) {
        int u = idx / (81 * 64);
        int r = idx - u * 81 * 64;
        int tap = r / 64;
        int oc = r - tap * 64;
        g_w1t[idx] = w1[(u * 64 + oc) * 81 + tap];
    }
    if (idx < 17 * 4 * 25 * 2 * 32) {
        int l = idx & 31;
        int m = (idx >> 5) & 1;
        int rest = idx >> 6;             // (u*4+ch)*25 + tap
        int tap = rest % 25;
        int rest2 = rest / 25;
        int ch = rest2 & 3;
        int u = rest2 >> 2;
        int g = l >> 2, t = l & 3;
        int oc0 = m * 16 + g;
        int ic0 = ch * 16;
        __half h[8];
#pragma unroll
        for (int q = 0; q < 8; q++) {
            int oc = oc0 + ((q >> 1) & 1) * 8;
            int ic = ic0 + 2 * t + (q & 1) + (q >> 2) * 8;
            h[q] = __float2half_rn(w2[((size_t)(u * 32 + oc) * 64 + ic) * 25 + tap]);
        }
        __half* dst = g_w2h + (size_t)idx * 8;
#pragma unroll
        for (int q = 0; q < 8; q++) dst[q] = h[q];
    }
}

// ---------------------------------------------------------------------------
// conv1: 9x9, 1 -> 64, ReLU; fp32 math, fp16 output in [z][H][W][64].
// ---------------------------------------------------------------------------
__global__ __launch_bounds__(256) void conv1_kernel(
    const float* __restrict__ in, const float* __restrict__ wt,
    const float* __restrict__ bias, __half* __restrict__ out,
    int H, int W, int nu)
{
    __shared__ float s_in[24 * 24];
    __shared__ float s_w[81 * 64];

    int z = blockIdx.z;
    int u = z % nu;
    int b = z / nu;
    int tid = threadIdx.x;
    int x0 = blockIdx.x * 16, y0 = blockIdx.y * 16;
    const float* inb = in + (size_t)b * H * W;
    const float* wu = wt + (size_t)u * 5184;

    for (int i = tid; i < 576; i += 256) {
        int iy = i / 24, ix = i - iy * 24;
        int gy = y0 + iy - 4, gx = x0 + ix - 4;
        float v = 0.f;
        if (gy >= 0 && gy < H && gx >= 0 && gx < W) v = inb[(size_t)gy * W + gx];
        s_in[i] = v;
    }
    for (int i = tid; i < 5184; i += 256) s_w[i] = wu[i];
    __syncthreads();

    int ocg = tid >> 6;
    int pt = tid & 63;
    int row = pt >> 2;
    int cgx = (pt & 3) * 4;

    float acc[4][16];
#pragma unroll
    for (int j = 0; j < 4; j++)
#pragma unroll
        for (int c = 0; c < 16; c++) acc[j][c] = 0.f;

    for (int dy = 0; dy < 9; dy++) {
        const float* ipb = &s_in[(row + dy) * 24 + cgx];
        const float* wpb = &s_w[dy * 9 * 64 + ocg * 16];
#pragma unroll
        for (int dx = 0; dx < 9; dx++) {
            float iv[4];
#pragma unroll
            for (int j = 0; j < 4; j++) iv[j] = ipb[dx + j];
            const float* wp = wpb + dx * 64;
            float4 w0 = *(const float4*)(wp);
            float4 w1v = *(const float4*)(wp + 4);
            float4 w2v = *(const float4*)(wp + 8);
            float4 w3v = *(const float4*)(wp + 12);
            float wv[16] = {w0.x, w0.y, w0.z, w0.w, w1v.x, w1v.y, w1v.z, w1v.w,
                            w2v.x, w2v.y, w2v.z, w2v.w, w3v.x, w3v.y, w3v.z, w3v.w};
#pragma unroll
            for (int j = 0; j < 4; j++)
#pragma unroll
                for (int c = 0; c < 16; c++) acc[j][c] += iv[j] * wv[c];
        }
    }

    float bvv[16];
#pragma unroll
    for (int c = 0; c < 16; c++) bvv[c] = bias[u * 64 + ocg * 16 + c];

    int y = y0 + row;
#pragma unroll
    for (int j = 0; j < 4; j++) {
        __align__(16) __half h[16];
#pragma unroll
        for (int c = 0; c < 16; c++)
            h[c] = __float2half_rn(fmaxf(acc[j][c] + bvv[c], 0.f));
        __half* op = out + (((size_t)z * H + y) * W + x0 + cgx + j) * 64 + ocg * 16;
        *(uint4*)op = *(uint4*)h;
        *(uint4*)(op + 8) = *(uint4*)(h + 8);
    }
}

// ---------------------------------------------------------------------------
// conv2: 5x5, 64 -> 32, ReLU via fp16 mma.sync.m16n8k16.
// Block 256 thr (8 warps), 16x16 px tile, 32 oc.
// Warp: rows 2w,2w+1 (32 px) x 32 oc = 2 M-tiles x 4 N-tiles; K = ic chunks of 16.
// ---------------------------------------------------------------------------
__device__ __forceinline__ void mma_f16(float c[4], const uint4& a,
                                        unsigned b0, unsigned b1) {
    asm volatile(
        "mma.sync.aligned.m16n8k16.row.col.f32.f16.f16.f32 "
        "{%0,%1,%2,%3}, {%4,%5,%6,%7}, {%8,%9}, {%0,%1,%2,%3};"
        : "+f"(c[0]), "+f"(c[1]), "+f"(c[2]), "+f"(c[3])
        : "r"(a.x), "r"(a.y), "r"(a.z), "r"(a.w), "r"(b0), "r"(b1));
}

__global__ __launch_bounds__(256) void conv2_mma_kernel(
    const __half* __restrict__ in,    // [z][H][W][64] fp16
    const __half* __restrict__ wt,    // [nu][4][25][2][32][8] fragment-major
    const float* __restrict__ bias,   // [nu][32]
    float* __restrict__ out,          // [z][32][H][W] fp32
    int H, int W, int nu)
{
    __shared__ __half s_raw[400 * 16];       // [site=20x20][16 ic]
    __shared__ __half s_w[25 * 2 * 32 * 8];  // [tap][m][lane][8]

    int z = blockIdx.z;
    int u = z % nu;
    int tid = threadIdx.x;
    int warp = tid >> 5;
    int lane = tid & 31;
    int x0 = blockIdx.x * 16, y0 = blockIdx.y * 16;
    const __half* inz = in + (size_t)z * H * W * 64;
    const __half* wu = wt + (size_t)u * 4 * 12800;

    int g = lane >> 2, t = lane & 3;
    int r0 = warp * 2;

    int bbase[4];
#pragma unroll
    for (int j = 0; j < 4; j++)
        bbase[j] = ((r0 + (j >> 1)) * 20 + (j & 1) * 8 + g) * 16 + 2 * t;

    float c[2][4][4];
#pragma unroll
    for (int m = 0; m < 2; m++)
#pragma unroll
        for (int j = 0; j < 4; j++)
#pragma unroll
            for (int q = 0; q < 4; q++) c[m][j][q] = 0.f;

    for (int ch = 0; ch < 4; ch++) {
        __syncthreads();
        // halo: 400 sites x 16 ic, as 800 16B transfers
#pragma unroll
        for (int l = 0; l < 4; l++) {
            int i = tid + l * 256;
            if (i < 800) {
                int site = i >> 1, part = i & 1;
                int py = site / 20, px = site - py * 20;
                int gy = y0 + py - 2, gx = x0 + px - 2;
                uint4 v = make_uint4(0, 0, 0, 0);
                if (gy >= 0 && gy < H && gx >= 0 && gx < W)
                    v = *(const uint4*)&inz[((size_t)gy * W + gx) * 64 + ch * 16 + part * 8];
                *(uint4*)&s_raw[site * 16 + part * 8] = v;
            }
        }
        // weights: 25*2*32*8 halves = 1600 16B transfers, linear copy
        const uint4* wsrc = (const uint4*)(wu + (size_t)ch * 12800);
#pragma unroll
        for (int l = 0; l < 7; l++) {
            int i = tid + l * 256;
            if (i < 1600) ((uint4*)s_w)[i] = wsrc[i];
        }
        __syncthreads();

#pragma unroll
        for (int dy = 0; dy < 5; dy++) {
#pragma unroll
            for (int dx = 0; dx < 5; dx++) {
                int tap = dy * 5 + dx;
                int toff = (dy * 20 + dx) * 16;
                uint4 a0 = *(const uint4*)&s_w[(size_t)(tap * 2 + 0) * 256 + lane * 8];
                uint4 a1 = *(const uint4*)&s_w[(size_t)(tap * 2 + 1) * 256 + lane * 8];
#pragma unroll
                for (int j = 0; j < 4; j++) {
                    unsigned b0 = *(const unsigned*)&s_raw[bbase[j] + toff];
                    unsigned b1 = *(const unsigned*)&s_raw[bbase[j] + toff + 8];
                    mma_f16(c[0][j], a0, b0, b1);
                    mma_f16(c[1][j], a1, b0, b1);
                }
            }
        }
    }

    // epilogue: oc = m*16 + g (+8), y = y0 + r0 + (j>>1), x = x0 + (j&1)*8 + 2*t
#pragma unroll
    for (int m = 0; m < 2; m++) {
        int oc0 = m * 16 + g;
        float bv0 = bias[u * 32 + oc0];
        float bv1 = bias[u * 32 + oc0 + 8];
#pragma unroll
        for (int j = 0; j < 4; j++) {
            int y = y0 + r0 + (j >> 1);
            int x = x0 + (j & 1) * 8 + 2 * t;
            float2 v0, v1;
            v0.x = fmaxf(c[m][j][0] + bv0, 0.f);
            v0.y = fmaxf(c[m][j][1] + bv0, 0.f);
            v1.x = fmaxf(c[m][j][2] + bv1, 0.f);
            v1.y = fmaxf(c[m][j][3] + bv1, 0.f);
            *(float2*)(out + ((size_t)z * 32 + oc0) * H * W + (size_t)y * W + x) = v0;
            *(float2*)(out + ((size_t)z * 32 + oc0 + 8) * H * W + (size_t)y * W + x) = v1;
        }
    }
}

// ---------------------------------------------------------------------------
// conv3: 5x5, 32 -> 1, no ReLU, optional 2x2 interleaved scatter.
// ---------------------------------------------------------------------------
__global__ __launch_bounds__(256) void conv3_kernel(
    const float* __restrict__ in, const float* __restrict__ w3,
    const float* __restrict__ b3, float* __restrict__ out,
    int H, int W, int nu, int interleave)
{
    __shared__ float s_in[16][400];
    __shared__ float s_w[16 * 25];

    int z = blockIdx.z;
    int u = z % nu;
    int b = z / nu;
    int tid = threadIdx.x;
    int x0 = blockIdx.x * 16, y0 = blockIdx.y * 16;
    int ty = tid >> 4, tx = tid & 15;
    const float* inz = in + (size_t)z * 32 * H * W;

    float acc = b3[u];

    for (int icb = 0; icb < 32; icb += 16) {
        __syncthreads();
        for (int i = tid; i < 6400; i += 256) {
            int ic = i / 400;
            int r = i - ic * 400;
            int iy = r / 20, ix = r - iy * 20;
            int gy = y0 + iy - 2, gx = x0 + ix - 2;
            float v = 0.f;
            if (gy >= 0 && gy < H && gx >= 0 && gx < W)
                v = inz[(size_t)(icb + ic) * H * W + (size_t)gy * W + gx];
            s_in[ic][r] = v;
        }
        for (int i = tid; i < 400; i += 256)
            s_w[i] = w3[(size_t)u * 800 + icb * 25 + i];
        __syncthreads();

        for (int ic = 0; ic < 16; ic++) {
#pragma unroll
            for (int dy = 0; dy < 5; dy++)
#pragma unroll
                for (int dx = 0; dx < 5; dx++)
                    acc += s_in[ic][(ty + dy) * 20 + tx + dx] * s_w[ic * 25 + dy * 5 + dx];
        }
    }

    int y = y0 + ty, x = x0 + tx;
    if (interleave) {
        int uy = u >> 1, ux = u & 1;
        out[(size_t)b * 4 * H * W + (size_t)(2 * y + uy) * (2 * W) + 2 * x + ux] = acc;
    } else {
        out[(size_t)b * H * W + (size_t)y * W + x] = acc;
    }
}

// ---------------------------------------------------------------------------
// msf_in = up8(x2) + up4(x4) + up2(x8) + x16  (bilinear half-pixel, clamp)
// ---------------------------------------------------------------------------
__device__ __forceinline__ float bilin(const float* __restrict__ p, int N,
                                       float inv_s, int y, int x) {
    float sy = (y + 0.5f) * inv_s - 0.5f;
    float sx = (x + 0.5f) * inv_s - 0.5f;
    float fy0 = floorf(sy), fx0 = floorf(sx);
    float fy = sy - fy0, fx = sx - fx0;
    int y0 = (int)fy0, x0 = (int)fx0;
    int y0c = min(max(y0, 0), N - 1);
    int y1c = min(max(y0 + 1, 0), N - 1);
    int x0c = min(max(x0, 0), N - 1);
    int x1c = min(max(x0 + 1, 0), N - 1);
    float v00 = p[(size_t)y0c * N + x0c];
    float v01 = p[(size_t)y0c * N + x1c];
    float v10 = p[(size_t)y1c * N + x0c];
    float v11 = p[(size_t)y1c * N + x1c];
    return (1.f - fy) * ((1.f - fx) * v00 + fx * v01) +
           fy * ((1.f - fx) * v10 + fx * v11);
}

__global__ void msf_in_kernel(const float* __restrict__ x2,
                              const float* __restrict__ x4,
                              const float* __restrict__ x8,
                              const float* __restrict__ x16,
                              float* __restrict__ out) {
    int idx = blockIdx.x * 256 + threadIdx.x;
    if (idx >= 2 * 1024 * 1024) return;
    int b = idx >> 20;
    int r = idx & 0xFFFFF;
    int y = r >> 10, x = r & 1023;
    float v = x16[idx];
    v += bilin(x2 + (size_t)b * 128 * 128, 128, 0.125f, y, x);
    v += bilin(x4 + (size_t)b * 256 * 256, 256, 0.25f, y, x);
    v += bilin(x8 + (size_t)b * 512 * 512, 512, 0.5f, y, x);
    out[idx] = v;
}

// ---------------------------------------------------------------------------
// Host orchestration
// ---------------------------------------------------------------------------
extern "C" void kernel_launch(void* const* d_in, const int* in_sizes, int n_in,
                              void* d_out, int out_size) {
    const float* image = (const float*)d_in[0];
    const float* w1 = (const float*)d_in[1];
    const float* b1 = (const float*)d_in[2];
    const float* w2 = (const float*)d_in[3];
    const float* b2 = (const float*)d_in[4];
    const float* w3 = (const float*)d_in[5];
    const float* b3 = (const float*)d_in[6];
    float* out = (float*)d_out;

    __half *t1h, *w2h;
    float *t2, *msf, *w1t;
    cudaGetSymbolAddress((void**)&t1h, g_t1h);
    cudaGetSymbolAddress((void**)&t2, g_t2);
    cudaGetSymbolAddress((void**)&msf, g_msf);
    cudaGetSymbolAddress((void**)&w1t, g_w1t);
    cudaGetSymbolAddress((void**)&w2h, g_w2h);

    prep_weights_kernel<<<(17 * 4 * 25 * 2 * 32 + 255) / 256, 256>>>(w1, w2);

    float* ox2 = out + 0;
    float* ox4 = out + 32768;
    float* ox8 = out + 163840;
    float* ox16 = out + 688128;
    float* omsf = out + 2785280;

    auto run_stage = [&](const float* inp, int H, int W, int ubase,
                         float* outp, int nu, int il) {
        dim3 g(W / 16, H / 16, 2 * nu);
        conv1_kernel<<<g, 256>>>(inp, w1t + (size_t)ubase * 5184,
                                 b1 + (size_t)ubase * 64, t1h, H, W, nu);
        conv2_mma_kernel<<<g, 256>>>(t1h, w2h + (size_t)ubase * 4 * 12800,
                                     b2 + (size_t)ubase * 32, t2, H, W, nu);
        conv3_kernel<<<g, 256>>>(t2, w3 + (size_t)ubase * 800,
                                 b3 + ubase, outp, H, W, nu, il);
    };

    run_stage(image, 64, 64, 0, ox2, 4, 1);
    run_stage(ox2, 128, 128, 4, ox4, 4, 1);
    run_stage(ox4, 256, 256, 8, ox8, 4, 1);
    run_stage(ox8, 512, 512, 12, ox16, 4, 1);

    msf_in_kernel<<<(2 * 1024 * 1024) / 256, 256>>>(ox2, ox4, ox8, ox16, msf);

    run_stage(msf, 1024, 1024, 16, omsf, 1, 0);
}

// round 5
// speedup vs baseline: 1.2487x; 1.2487x over previous
#include <cuda_runtime.h>
#include <cuda_fp16.h>
#include <cstdint>

// ---------------------------------------------------------------------------
// DSDMSR multi-scale SRCNN cascade.
// conv1 (9x9,1->64): fp16 mma with split hi/lo activations (error-compensated).
// conv2 (5x5,64->32): fp16 mma.sync m16n8k16.
// conv3 (5x5,32->1): fp32.
// ---------------------------------------------------------------------------

__device__ __half g_t1h[134217728];          // conv1 out, [z][H][W][64] fp16 (256MB)
__device__ float  g_t2[67108864];            // conv2 out, [z][32][H][W] fp32 (256MB)
__device__ float  g_msf[2 * 1024 * 1024];
__device__ __half g_w1h[17 * 6 * 8 * 32 * 4];        // conv1 weights fragment-major
__device__ __half g_w2h[17 * 4 * 25 * 2 * 32 * 8];   // conv2 weights fragment-major

__device__ __forceinline__ unsigned pkh(__half a, __half b) {
    __half2 p = __halves2half2(a, b);
    return *(unsigned*)&p;
}

// ---------------------------------------------------------------------------
// Weight prep.
// w1 frag-major: [u][kc(6)][nt(8)][lane(32)][4]; lane(g=l>>2,t=l&3):
//   {W[nt*8+g][kc*16+2t], [2t+1], [2t+8], [2t+9]}, taps>=81 -> 0.
// w2 frag-major: [u][ch(4)][tap(25)][m(2)][lane(32)][8] (as in R4).
// ---------------------------------------------------------------------------
__global__ void prep_weights_kernel(const float* __restrict__ w1,
                                    const float* __restrict__ w2) {
    int idx = blockIdx.x * 256 + threadIdx.x;
    if (idx < 17 * 6 * 8 * 32) {
        int lane = idx & 31;
        int r = idx >> 5;
        int nt = r & 7; r >>= 3;
        int kc = r % 6;
        int u = r / 6;
        int g = lane >> 2, t = lane & 3;
        int oc = nt * 8 + g;
        int kt[4] = {kc * 16 + 2 * t, kc * 16 + 2 * t + 1,
                     kc * 16 + 2 * t + 8, kc * 16 + 2 * t + 9};
        __half* dst = g_w1h + (size_t)idx * 4;
#pragma unroll
        for (int q = 0; q < 4; q++)
            dst[q] = (kt[q] < 81)
                ? __float2half_rn(w1[((size_t)u * 64 + oc) * 81 + kt[q]])
                : __half(0.f);
    }
    if (idx < 17 * 4 * 25 * 2 * 32) {
        int l = idx & 31;
        int m = (idx >> 5) & 1;
        int rest = idx >> 6;
        int tap = rest % 25;
        int rest2 = rest / 25;
        int ch = rest2 & 3;
        int u = rest2 >> 2;
        int g = l >> 2, t = l & 3;
        int oc0 = m * 16 + g;
        int ic0 = ch * 16;
        __half* dst = g_w2h + (size_t)idx * 8;
#pragma unroll
        for (int q = 0; q < 8; q++) {
            int oc = oc0 + ((q >> 1) & 1) * 8;
            int ic = ic0 + 2 * t + (q & 1) + (q >> 2) * 8;
            dst[q] = __float2half_rn(w2[((size_t)(u * 32 + oc) * 64 + ic) * 25 + tap]);
        }
    }
}

// ---------------------------------------------------------------------------
// conv1: 9x9, 1->64, ReLU via fp16 mma m16n8k16, split activations.
// A = im2col(x) [M=px, K=96 padded taps], B = w1 [K][N=oc].
// Block 256 thr (8 warps), 16x16 px tile; warp handles rows 2w,2w+1.
// Output fp16 [z][H][W][64].
// ---------------------------------------------------------------------------
__device__ __forceinline__ void mma_f16(float c[4], const uint4& a,
                                        unsigned b0, unsigned b1) {
    asm volatile(
        "mma.sync.aligned.m16n8k16.row.col.f32.f16.f16.f32 "
        "{%0,%1,%2,%3}, {%4,%5,%6,%7}, {%8,%9}, {%0,%1,%2,%3};"
        : "+f"(c[0]), "+f"(c[1]), "+f"(c[2]), "+f"(c[3])
        : "r"(a.x), "r"(a.y), "r"(a.z), "r"(a.w), "r"(b0), "r"(b1));
}

__global__ __launch_bounds__(256) void conv1_mma_kernel(
    const float* __restrict__ in,    // [2][H][W] fp32
    const __half* __restrict__ wt,   // [nu][6][8][32][4] frag-major
    const float* __restrict__ bias,  // [nu][64]
    __half* __restrict__ out,        // [z][H][W][64]
    int H, int W, int nu)
{
    __shared__ __half s_h[24 * 24];
    __shared__ __half s_l[24 * 24];
    __shared__ __half s_w[6144];
    __shared__ float s_b[64];

    int z = blockIdx.z;
    int u = z % nu;
    int b = z / nu;
    int tid = threadIdx.x;
    int warp = tid >> 5;
    int lane = tid & 31;
    int x0 = blockIdx.x * 16, y0 = blockIdx.y * 16;
    const float* inb = in + (size_t)b * H * W;
    const __half* wu = wt + (size_t)u * 6144;

    for (int i = tid; i < 576; i += 256) {
        int iy = i / 24, ix = i - iy * 24;
        int gy = y0 + iy - 4, gx = x0 + ix - 4;
        float v = 0.f;
        if (gy >= 0 && gy < H && gx >= 0 && gx < W) v = inb[(size_t)gy * W + gx];
        __half h = __float2half_rn(v);
        s_h[i] = h;
        s_l[i] = __float2half_rn(v - __half2float(h));
    }
    for (int i = tid; i < 768; i += 256)
        ((uint4*)s_w)[i] = ((const uint4*)wu)[i];
    if (tid < 64) s_b[tid] = bias[u * 64 + tid];
    __syncthreads();

    int g = lane >> 2, t = lane & 3;
    int r0 = warp * 2;

    float c[2][8][4];
#pragma unroll
    for (int m = 0; m < 2; m++)
#pragma unroll
        for (int nt = 0; nt < 8; nt++)
#pragma unroll
            for (int q = 0; q < 4; q++) c[m][nt][q] = 0.f;

#pragma unroll
    for (int kc = 0; kc < 6; kc++) {
        // B regs: 8 n-tiles
        uint2 breg[8];
#pragma unroll
        for (int nt = 0; nt < 8; nt++)
            breg[nt] = *(const uint2*)&s_w[((kc * 8 + nt) * 32 + lane) * 4];

        // tap offsets for this thread (clamped into valid range; pad weights=0)
        int o[4];
#pragma unroll
        for (int q = 0; q < 4; q++) {
            int tap = kc * 16 + 2 * t + (q & 1) + (q >> 1) * 8;
            tap = min(tap, 80);
            int dy = tap / 9, dx = tap - 9 * dy;
            o[q] = dy * 24 + dx;
        }

#pragma unroll
        for (int mrow = 0; mrow < 2; mrow++) {
            int base = (r0 + mrow) * 24;
            const __half* sh = s_h + base;
            const __half* sl = s_l + base;
            uint4 ah, al;
            ah.x = pkh(sh[o[0] + g],     sh[o[1] + g]);
            ah.y = pkh(sh[o[0] + g + 8], sh[o[1] + g + 8]);
            ah.z = pkh(sh[o[2] + g],     sh[o[3] + g]);
            ah.w = pkh(sh[o[2] + g + 8], sh[o[3] + g + 8]);
            al.x = pkh(sl[o[0] + g],     sl[o[1] + g]);
            al.y = pkh(sl[o[0] + g + 8], sl[o[1] + g + 8]);
            al.z = pkh(sl[o[2] + g],     sl[o[3] + g]);
            al.w = pkh(sl[o[2] + g + 8], sl[o[3] + g + 8]);
#pragma unroll
            for (int nt = 0; nt < 8; nt++) {
                mma_f16(c[mrow][nt], ah, breg[nt].x, breg[nt].y);
                mma_f16(c[mrow][nt], al, breg[nt].x, breg[nt].y);
            }
        }
    }

    // epilogue: C[px][oc]; c0,c1 = px g, oc 2t,2t+1; c2,c3 = px g+8.
#pragma unroll
    for (int mrow = 0; mrow < 2; mrow++) {
        int y = y0 + r0 + mrow;
#pragma unroll
        for (int nt = 0; nt < 8; nt++) {
            int oc0 = nt * 8 + 2 * t;
            float bv0 = s_b[oc0], bv1 = s_b[oc0 + 1];
            __half2 v0 = __halves2half2(
                __float2half_rn(fmaxf(c[mrow][nt][0] + bv0, 0.f)),
                __float2half_rn(fmaxf(c[mrow][nt][1] + bv1, 0.f)));
            __half2 v1 = __halves2half2(
                __float2half_rn(fmaxf(c[mrow][nt][2] + bv0, 0.f)),
                __float2half_rn(fmaxf(c[mrow][nt][3] + bv1, 0.f)));
            *(__half2*)(out + (((size_t)z * H + y) * W + x0 + g) * 64 + oc0) = v0;
            *(__half2*)(out + (((size_t)z * H + y) * W + x0 + g + 8) * 64 + oc0) = v1;
        }
    }
}

// ---------------------------------------------------------------------------
// conv2: 5x5, 64 -> 32, ReLU via fp16 mma.sync.m16n8k16 (unchanged from R4).
// ---------------------------------------------------------------------------
__global__ __launch_bounds__(256) void conv2_mma_kernel(
    const __half* __restrict__ in,    // [z][H][W][64] fp16
    const __half* __restrict__ wt,    // [nu][4][25][2][32][8] fragment-major
    const float* __restrict__ bias,   // [nu][32]
    float* __restrict__ out,          // [z][32][H][W] fp32
    int H, int W, int nu)
{
    __shared__ __half s_raw[400 * 16];
    __shared__ __half s_w[25 * 2 * 32 * 8];

    int z = blockIdx.z;
    int u = z % nu;
    int tid = threadIdx.x;
    int warp = tid >> 5;
    int lane = tid & 31;
    int x0 = blockIdx.x * 16, y0 = blockIdx.y * 16;
    const __half* inz = in + (size_t)z * H * W * 64;
    const __half* wu = wt + (size_t)u * 4 * 12800;

    int g = lane >> 2, t = lane & 3;
    int r0 = warp * 2;

    int bbase[4];
#pragma unroll
    for (int j = 0; j < 4; j++)
        bbase[j] = ((r0 + (j >> 1)) * 20 + (j & 1) * 8 + g) * 16 + 2 * t;

    float c[2][4][4];
#pragma unroll
    for (int m = 0; m < 2; m++)
#pragma unroll
        for (int j = 0; j < 4; j++)
#pragma unroll
            for (int q = 0; q < 4; q++) c[m][j][q] = 0.f;

    for (int ch = 0; ch < 4; ch++) {
        __syncthreads();
#pragma unroll
        for (int l = 0; l < 4; l++) {
            int i = tid + l * 256;
            if (i < 800) {
                int site = i >> 1, part = i & 1;
                int py = site / 20, px = site - py * 20;
                int gy = y0 + py - 2, gx = x0 + px - 2;
                uint4 v = make_uint4(0, 0, 0, 0);
                if (gy >= 0 && gy < H && gx >= 0 && gx < W)
                    v = *(const uint4*)&inz[((size_t)gy * W + gx) * 64 + ch * 16 + part * 8];
                *(uint4*)&s_raw[site * 16 + part * 8] = v;
            }
        }
        const uint4* wsrc = (const uint4*)(wu + (size_t)ch * 12800);
#pragma unroll
        for (int l = 0; l < 7; l++) {
            int i = tid + l * 256;
            if (i < 1600) ((uint4*)s_w)[i] = wsrc[i];
        }
        __syncthreads();

#pragma unroll
        for (int dy = 0; dy < 5; dy++) {
#pragma unroll
            for (int dx = 0; dx < 5; dx++) {
                int tap = dy * 5 + dx;
                int toff = (dy * 20 + dx) * 16;
                uint4 a0 = *(const uint4*)&s_w[(size_t)(tap * 2 + 0) * 256 + lane * 8];
                uint4 a1 = *(const uint4*)&s_w[(size_t)(tap * 2 + 1) * 256 + lane * 8];
#pragma unroll
                for (int j = 0; j < 4; j++) {
                    unsigned b0 = *(const unsigned*)&s_raw[bbase[j] + toff];
                    unsigned b1 = *(const unsigned*)&s_raw[bbase[j] + toff + 8];
                    mma_f16(c[0][j], a0, b0, b1);
                    mma_f16(c[1][j], a1, b0, b1);
                }
            }
        }
    }

#pragma unroll
    for (int m = 0; m < 2; m++) {
        int oc0 = m * 16 + g;
        float bv0 = bias[u * 32 + oc0];
        float bv1 = bias[u * 32 + oc0 + 8];
#pragma unroll
        for (int j = 0; j < 4; j++) {
            int y = y0 + r0 + (j >> 1);
            int x = x0 + (j & 1) * 8 + 2 * t;
            float2 v0, v1;
            v0.x = fmaxf(c[m][j][0] + bv0, 0.f);
            v0.y = fmaxf(c[m][j][1] + bv0, 0.f);
            v1.x = fmaxf(c[m][j][2] + bv1, 0.f);
            v1.y = fmaxf(c[m][j][3] + bv1, 0.f);
            *(float2*)(out + ((size_t)z * 32 + oc0) * H * W + (size_t)y * W + x) = v0;
            *(float2*)(out + ((size_t)z * 32 + oc0 + 8) * H * W + (size_t)y * W + x) = v1;
        }
    }
}

// ---------------------------------------------------------------------------
// conv3: 5x5, 32 -> 1, no ReLU, optional 2x2 interleaved scatter.
// ---------------------------------------------------------------------------
__global__ __launch_bounds__(256) void conv3_kernel(
    const float* __restrict__ in, const float* __restrict__ w3,
    const float* __restrict__ b3, float* __restrict__ out,
    int H, int W, int nu, int interleave)
{
    __shared__ float s_in[16][400];
    __shared__ float s_w[16 * 25];

    int z = blockIdx.z;
    int u = z % nu;
    int b = z / nu;
    int tid = threadIdx.x;
    int x0 = blockIdx.x * 16, y0 = blockIdx.y * 16;
    int ty = tid >> 4, tx = tid & 15;
    const float* inz = in + (size_t)z * 32 * H * W;

    float acc = b3[u];

    for (int icb = 0; icb < 32; icb += 16) {
        __syncthreads();
        for (int i = tid; i < 6400; i += 256) {
            int ic = i / 400;
            int r = i - ic * 400;
            int iy = r / 20, ix = r - iy * 20;
            int gy = y0 + iy - 2, gx = x0 + ix - 2;
            float v = 0.f;
            if (gy >= 0 && gy < H && gx >= 0 && gx < W)
                v = inz[(size_t)(icb + ic) * H * W + (size_t)gy * W + gx];
            s_in[ic][r] = v;
        }
        for (int i = tid; i < 400; i += 256)
            s_w[i] = w3[(size_t)u * 800 + icb * 25 + i];
        __syncthreads();

        for (int ic = 0; ic < 16; ic++) {
#pragma unroll
            for (int dy = 0; dy < 5; dy++)
#pragma unroll
                for (int dx = 0; dx < 5; dx++)
                    acc += s_in[ic][(ty + dy) * 20 + tx + dx] * s_w[ic * 25 + dy * 5 + dx];
        }
    }

    int y = y0 + ty, x = x0 + tx;
    if (interleave) {
        int uy = u >> 1, ux = u & 1;
        out[(size_t)b * 4 * H * W + (size_t)(2 * y + uy) * (2 * W) + 2 * x + ux] = acc;
    } else {
        out[(size_t)b * H * W + (size_t)y * W + x] = acc;
    }
}

// ---------------------------------------------------------------------------
// msf_in = up8(x2) + up4(x4) + up2(x8) + x16  (bilinear half-pixel, clamp)
// ---------------------------------------------------------------------------
__device__ __forceinline__ float bilin(const float* __restrict__ p, int N,
                                       float inv_s, int y, int x) {
    float sy = (y + 0.5f) * inv_s - 0.5f;
    float sx = (x + 0.5f) * inv_s - 0.5f;
    float fy0 = floorf(sy), fx0 = floorf(sx);
    float fy = sy - fy0, fx = sx - fx0;
    int y0 = (int)fy0, x0 = (int)fx0;
    int y0c = min(max(y0, 0), N - 1);
    int y1c = min(max(y0 + 1, 0), N - 1);
    int x0c = min(max(x0, 0), N - 1);
    int x1c = min(max(x0 + 1, 0), N - 1);
    float v00 = p[(size_t)y0c * N + x0c];
    float v01 = p[(size_t)y0c * N + x1c];
    float v10 = p[(size_t)y1c * N + x0c];
    float v11 = p[(size_t)y1c * N + x1c];
    return (1.f - fy) * ((1.f - fx) * v00 + fx * v01) +
           fy * ((1.f - fx) * v10 + fx * v11);
}

__global__ void msf_in_kernel(const float* __restrict__ x2,
                              const float* __restrict__ x4,
                              const float* __restrict__ x8,
                              const float* __restrict__ x16,
                              float* __restrict__ out) {
    int idx = blockIdx.x * 256 + threadIdx.x;
    if (idx >= 2 * 1024 * 1024) return;
    int b = idx >> 20;
    int r = idx & 0xFFFFF;
    int y = r >> 10, x = r & 1023;
    float v = x16[idx];
    v += bilin(x2 + (size_t)b * 128 * 128, 128, 0.125f, y, x);
    v += bilin(x4 + (size_t)b * 256 * 256, 256, 0.25f, y, x);
    v += bilin(x8 + (size_t)b * 512 * 512, 512, 0.5f, y, x);
    out[idx] = v;
}

// ---------------------------------------------------------------------------
// Host orchestration
// ---------------------------------------------------------------------------
extern "C" void kernel_launch(void* const* d_in, const int* in_sizes, int n_in,
                              void* d_out, int out_size) {
    const float* image = (const float*)d_in[0];
    const float* w1 = (const float*)d_in[1];
    const float* b1 = (const float*)d_in[2];
    const float* w2 = (const float*)d_in[3];
    const float* b2 = (const float*)d_in[4];
    const float* w3 = (const float*)d_in[5];
    const float* b3 = (const float*)d_in[6];
    float* out = (float*)d_out;

    __half *t1h, *w1h, *w2h;
    float *t2, *msf;
    cudaGetSymbolAddress((void**)&t1h, g_t1h);
    cudaGetSymbolAddress((void**)&t2, g_t2);
    cudaGetSymbolAddress((void**)&msf, g_msf);
    cudaGetSymbolAddress((void**)&w1h, g_w1h);
    cudaGetSymbolAddress((void**)&w2h, g_w2h);

    prep_weights_kernel<<<(17 * 4 * 25 * 2 * 32 + 255) / 256, 256>>>(w1, w2);

    float* ox2 = out + 0;
    float* ox4 = out + 32768;
    float* ox8 = out + 163840;
    float* ox16 = out + 688128;
    float* omsf = out + 2785280;

    auto run_stage = [&](const float* inp, int H, int W, int ubase,
                         float* outp, int nu, int il) {
        dim3 g(W / 16, H / 16, 2 * nu);
        conv1_mma_kernel<<<g, 256>>>(inp, w1h + (size_t)ubase * 6144,
                                     b1 + (size_t)ubase * 64, t1h, H, W, nu);
        conv2_mma_kernel<<<g, 256>>>(t1h, w2h + (size_t)ubase * 4 * 12800,
                                     b2 + (size_t)ubase * 32, t2, H, W, nu);
        conv3_kernel<<<g, 256>>>(t2, w3 + (size_t)ubase * 800,
                                 b3 + ubase, outp, H, W, nu, il);
    };

    run_stage(image, 64, 64, 0, ox2, 4, 1);
    run_stage(ox2, 128, 128, 4, ox4, 4, 1);
    run_stage(ox4, 256, 256, 8, ox8, 4, 1);
    run_stage(ox8, 512, 512, 12, ox16, 4, 1);

    msf_in_kernel<<<(2 * 1024 * 1024) / 256, 256>>>(ox2, ox4, ox8, ox16, msf);

    run_stage(msf, 1024, 1024, 16, omsf, 1, 0);
}

// round 7
// speedup vs baseline: 1.5604x; 1.2497x over previous
#include <cuda_runtime.h>
#include <cuda_fp16.h>
#include <cstdint>

// ---------------------------------------------------------------------------
// DSDMSR multi-scale SRCNN cascade (sm_100 / compute_100 legacy mma path).
// conv1 (9x9,1->64): fp16 mma, split hi/lo activations (compensated).
// conv2 (5x5,64->32): fp16 mma m16n8k16, double-buffered; epilogue -> (hi,lo).
// conv3 (5x5,32->1): site-GEMM on tensor pipe, 3-pass compensated + tap-sum.
// ---------------------------------------------------------------------------

__device__ __half g_t1h[134217728];          // conv1 out, [z][H][W][64] fp16
__device__ __half g_t2hl[134217728];         // conv2 out, [z][H][W][32*(hi,lo)]
__device__ float  g_msf[2 * 1024 * 1024];
__device__ __half g_w1h[17 * 6 * 8 * 32 * 4];      // conv1 w frag-major
__device__ __half g_w2h[17 * 4 * 25 * 2 * 32 * 8]; // conv2 w frag-major
__device__ __half g_w3f[17 * 2048];                // conv3 w frag-major (hi,lo)

__device__ __forceinline__ unsigned pkh(__half a, __half b) {
    __half2 p = __halves2half2(a, b);
    return *(unsigned*)&p;
}
__device__ __forceinline__ void mma_f16(float c[4], const uint4& a,
                                        unsigned b0, unsigned b1) {
    asm volatile(
        "mma.sync.aligned.m16n8k16.row.col.f32.f16.f16.f32 "
        "{%0,%1,%2,%3}, {%4,%5,%6,%7}, {%8,%9}, {%0,%1,%2,%3};"
        : "+f"(c[0]), "+f"(c[1]), "+f"(c[2]), "+f"(c[3])
        : "r"(a.x), "r"(a.y), "r"(a.z), "r"(a.w), "r"(b0), "r"(b1));
}
__device__ __forceinline__ void st_hl(__half* p, float v) {
    __half h = __float2half_rn(v);
    __half l = __float2half_rn(v - __half2float(h));
    *(__half2*)p = __halves2half2(h, l);
}

// ---------------------------------------------------------------------------
// Weight prep: w1 frag-major, w2 frag-major, w3 frag-major hi/lo.
// ---------------------------------------------------------------------------
__global__ void prep_weights_kernel(const float* __restrict__ w1,
                                    const float* __restrict__ w2,
                                    const float* __restrict__ w3) {
    int idx = blockIdx.x * 256 + threadIdx.x;
    if (idx < 17 * 6 * 8 * 32) {
        int lane = idx & 31;
        int r = idx >> 5;
        int nt = r & 7; r >>= 3;
        int kc = r % 6;
        int u = r / 6;
        int g = lane >> 2, t = lane & 3;
        int oc = nt * 8 + g;
        int kt[4] = {kc * 16 + 2 * t, kc * 16 + 2 * t + 1,
                     kc * 16 + 2 * t + 8, kc * 16 + 2 * t + 9};
        __half* dst = g_w1h + (size_t)idx * 4;
#pragma unroll
        for (int q = 0; q < 4; q++)
            dst[q] = (kt[q] < 81)
                ? __float2half_rn(w1[((size_t)u * 64 + oc) * 81 + kt[q]])
                : __half(0.f);
    }
    if (idx < 17 * 4 * 25 * 2 * 32) {
        int l = idx & 31;
        int m = (idx >> 5) & 1;
        int rest = idx >> 6;
        int tap = rest % 25;
        int rest2 = rest / 25;
        int ch = rest2 & 3;
        int u = rest2 >> 2;
        int g = l >> 2, t = l & 3;
        int oc0 = m * 16 + g;
        int ic0 = ch * 16;
        __half* dst = g_w2h + (size_t)idx * 8;
#pragma unroll
        for (int q = 0; q < 8; q++) {
            int oc = oc0 + ((q >> 1) & 1) * 8;
            int ic = ic0 + 2 * t + (q & 1) + (q >> 2) * 8;
            dst[q] = __float2half_rn(w2[((size_t)(u * 32 + oc) * 64 + ic) * 25 + tap]);
        }
    }
    // w3 frags: [u][hl(2)][nt(4)][ks(2)][lane(32)][4 halves]
    if (idx < 17 * 2 * 4 * 2 * 32) {
        int lane = idx & 31;
        int r = idx >> 5;
        int ks = r & 1; r >>= 1;
        int nt = r & 3; r >>= 2;
        int hl = r & 1; r >>= 1;
        int u = r;
        int g = lane >> 2, t = lane & 3;
        int tap = nt * 8 + g;
        __half* dst = g_w3f + (size_t)idx * 4;
#pragma unroll
        for (int q = 0; q < 4; q++) {
            int kq = ks * 16 + 2 * t + (q & 1) + (q >> 1) * 8;
            float v = (tap < 25) ? w3[(size_t)u * 800 + kq * 25 + tap] : 0.f;
            __half h = __float2half_rn(v);
            dst[q] = (hl == 0) ? h : __float2half_rn(v - __half2float(h));
        }
    }
}

// ---------------------------------------------------------------------------
// conv1: 9x9, 1->64, ReLU via fp16 mma, split activations (unchanged, R5).
// ---------------------------------------------------------------------------
__global__ __launch_bounds__(256) void conv1_mma_kernel(
    const float* __restrict__ in, const __half* __restrict__ wt,
    const float* __restrict__ bias, __half* __restrict__ out,
    int H, int W, int nu)
{
    __shared__ __half s_h[24 * 24];
    __shared__ __half s_l[24 * 24];
    __shared__ __half s_w[6144];
    __shared__ float s_b[64];

    int z = blockIdx.z;
    int u = z % nu;
    int b = z / nu;
    int tid = threadIdx.x;
    int warp = tid >> 5;
    int lane = tid & 31;
    int x0 = blockIdx.x * 16, y0 = blockIdx.y * 16;
    const float* inb = in + (size_t)b * H * W;
    const __half* wu = wt + (size_t)u * 6144;

    for (int i = tid; i < 576; i += 256) {
        int iy = i / 24, ix = i - iy * 24;
        int gy = y0 + iy - 4, gx = x0 + ix - 4;
        float v = 0.f;
        if (gy >= 0 && gy < H && gx >= 0 && gx < W) v = inb[(size_t)gy * W + gx];
        __half h = __float2half_rn(v);
        s_h[i] = h;
        s_l[i] = __float2half_rn(v - __half2float(h));
    }
    for (int i = tid; i < 768; i += 256)
        ((uint4*)s_w)[i] = ((const uint4*)wu)[i];
    if (tid < 64) s_b[tid] = bias[u * 64 + tid];
    __syncthreads();

    int g = lane >> 2, t = lane & 3;
    int r0 = warp * 2;

    float c[2][8][4];
#pragma unroll
    for (int m = 0; m < 2; m++)
#pragma unroll
        for (int nt = 0; nt < 8; nt++)
#pragma unroll
            for (int q = 0; q < 4; q++) c[m][nt][q] = 0.f;

#pragma unroll
    for (int kc = 0; kc < 6; kc++) {
        uint2 breg[8];
#pragma unroll
        for (int nt = 0; nt < 8; nt++)
            breg[nt] = *(const uint2*)&s_w[((kc * 8 + nt) * 32 + lane) * 4];

        int o[4];
#pragma unroll
        for (int q = 0; q < 4; q++) {
            int tap = kc * 16 + 2 * t + (q & 1) + (q >> 1) * 8;
            tap = min(tap, 80);
            int dy = tap / 9, dx = tap - 9 * dy;
            o[q] = dy * 24 + dx;
        }

#pragma unroll
        for (int mrow = 0; mrow < 2; mrow++) {
            int base = (r0 + mrow) * 24;
            const __half* sh = s_h + base;
            const __half* sl = s_l + base;
            uint4 ah, al;
            ah.x = pkh(sh[o[0] + g],     sh[o[1] + g]);
            ah.y = pkh(sh[o[0] + g + 8], sh[o[1] + g + 8]);
            ah.z = pkh(sh[o[2] + g],     sh[o[3] + g]);
            ah.w = pkh(sh[o[2] + g + 8], sh[o[3] + g + 8]);
            al.x = pkh(sl[o[0] + g],     sl[o[1] + g]);
            al.y = pkh(sl[o[0] + g + 8], sl[o[1] + g + 8]);
            al.z = pkh(sl[o[2] + g],     sl[o[3] + g]);
            al.w = pkh(sl[o[2] + g + 8], sl[o[3] + g + 8]);
#pragma unroll
            for (int nt = 0; nt < 8; nt++) {
                mma_f16(c[mrow][nt], ah, breg[nt].x, breg[nt].y);
                mma_f16(c[mrow][nt], al, breg[nt].x, breg[nt].y);
            }
        }
    }

#pragma unroll
    for (int mrow = 0; mrow < 2; mrow++) {
        int y = y0 + r0 + mrow;
#pragma unroll
        for (int nt = 0; nt < 8; nt++) {
            int oc0 = nt * 8 + 2 * t;
            float bv0 = s_b[oc0], bv1 = s_b[oc0 + 1];
            __half2 v0 = __halves2half2(
                __float2half_rn(fmaxf(c[mrow][nt][0] + bv0, 0.f)),
                __float2half_rn(fmaxf(c[mrow][nt][1] + bv1, 0.f)));
            __half2 v1 = __halves2half2(
                __float2half_rn(fmaxf(c[mrow][nt][2] + bv0, 0.f)),
                __float2half_rn(fmaxf(c[mrow][nt][3] + bv1, 0.f)));
            *(__half2*)(out + (((size_t)z * H + y) * W + x0 + g) * 64 + oc0) = v0;
            *(__half2*)(out + (((size_t)z * H + y) * W + x0 + g + 8) * 64 + oc0) = v1;
        }
    }
}

// ---------------------------------------------------------------------------
// conv2: 5x5, 64->32, ReLU via fp16 mma, double-buffered smem.
// Output: interleaved (hi,lo) fp16 pairs, [z][H][W][oc*2].
// ---------------------------------------------------------------------------
__global__ __launch_bounds__(256) void conv2_mma_kernel(
    const __half* __restrict__ in,    // [z][H][W][64] fp16
    const __half* __restrict__ wt,    // [nu][4][25][2][32][8] frag-major
    const float* __restrict__ bias,   // [nu][32]
    __half* __restrict__ out,         // [z][H][W][64] (hi,lo interleaved)
    int H, int W, int nu)
{
    extern __shared__ __half s2[];
    __half* s_raw = s2;            // [2][400*16]
    __half* s_wt  = s2 + 12800;    // [2][12800]

    int z = blockIdx.z;
    int u = z % nu;
    int tid = threadIdx.x;
    int warp = tid >> 5;
    int lane = tid & 31;
    int x0 = blockIdx.x * 16, y0 = blockIdx.y * 16;
    const __half* inz = in + (size_t)z * H * W * 64;
    const __half* wu = wt + (size_t)u * 4 * 12800;

    int g = lane >> 2, t = lane & 3;
    int r0 = warp * 2;

    int bbase[4];
#pragma unroll
    for (int j = 0; j < 4; j++)
        bbase[j] = ((r0 + (j >> 1)) * 20 + (j & 1) * 8 + g) * 16 + 2 * t;

    float c[2][4][4];
#pragma unroll
    for (int m = 0; m < 2; m++)
#pragma unroll
        for (int j = 0; j < 4; j++)
#pragma unroll
            for (int q = 0; q < 4; q++) c[m][j][q] = 0.f;

    auto load_chunk = [&](int ch) {
        __half* raw = s_raw + (ch & 1) * 6400;
        __half* ww  = s_wt  + (ch & 1) * 12800;
#pragma unroll
        for (int l = 0; l < 4; l++) {
            int i = tid + l * 256;
            if (i < 800) {
                int site = i >> 1, part = i & 1;
                int py = site / 20, px = site - py * 20;
                int gy = y0 + py - 2, gx = x0 + px - 2;
                uint4 v = make_uint4(0, 0, 0, 0);
                if (gy >= 0 && gy < H && gx >= 0 && gx < W)
                    v = *(const uint4*)&inz[((size_t)gy * W + gx) * 64 + ch * 16 + part * 8];
                *(uint4*)&raw[site * 16 + part * 8] = v;
            }
        }
        const uint4* wsrc = (const uint4*)(wu + (size_t)ch * 12800);
#pragma unroll
        for (int l = 0; l < 7; l++) {
            int i = tid + l * 256;
            if (i < 1600) ((uint4*)ww)[i] = wsrc[i];
        }
    };

    load_chunk(0);
    __syncthreads();

    for (int ch = 0; ch < 4; ch++) {
        if (ch < 3) load_chunk(ch + 1);
        const __half* raw = s_raw + (ch & 1) * 6400;
        const __half* sw  = s_wt  + (ch & 1) * 12800;

#pragma unroll
        for (int dy = 0; dy < 5; dy++) {
#pragma unroll
            for (int dx = 0; dx < 5; dx++) {
                int tap = dy * 5 + dx;
                int toff = (dy * 20 + dx) * 16;
                uint4 a0 = *(const uint4*)&sw[(size_t)(tap * 2 + 0) * 256 + lane * 8];
                uint4 a1 = *(const uint4*)&sw[(size_t)(tap * 2 + 1) * 256 + lane * 8];
#pragma unroll
                for (int j = 0; j < 4; j++) {
                    unsigned b0 = *(const unsigned*)&raw[bbase[j] + toff];
                    unsigned b1 = *(const unsigned*)&raw[bbase[j] + toff + 8];
                    mma_f16(c[0][j], a0, b0, b1);
                    mma_f16(c[1][j], a1, b0, b1);
                }
            }
        }
        __syncthreads();
    }

    // epilogue: rows oc = m*16+g (+8); cols px = (j-tile x) + {2t, 2t+1}
#pragma unroll
    for (int m = 0; m < 2; m++) {
        int oc0 = m * 16 + g;
        float bv0 = bias[u * 32 + oc0];
        float bv1 = bias[u * 32 + oc0 + 8];
#pragma unroll
        for (int j = 0; j < 4; j++) {
            int y = y0 + r0 + (j >> 1);
            int xb = x0 + (j & 1) * 8 + 2 * t;
            __half* base = out + (((size_t)z * H + y) * W + xb) * 64;
            st_hl(base + oc0 * 2,            fmaxf(c[m][j][0] + bv0, 0.f));
            st_hl(base + 64 + oc0 * 2,       fmaxf(c[m][j][1] + bv0, 0.f));
            st_hl(base + (oc0 + 8) * 2,      fmaxf(c[m][j][2] + bv1, 0.f));
            st_hl(base + 64 + (oc0 + 8) * 2, fmaxf(c[m][j][3] + bv1, 0.f));
        }
    }
}

// ---------------------------------------------------------------------------
// conv3: 5x5, 32->1 via site-GEMM D[site,tap] then fp32 tap-sum.
// 3 compensated passes: Ah*Wh + Al*Wh + Ah*Wl.  16x16 out tile, 256 thr.
// ---------------------------------------------------------------------------
#define C3_AL_OFF  36864
#define C3_WF_OFF  73728
#define C3_SMEM    77824

__global__ __launch_bounds__(256) void conv3_mma_kernel(
    const __half* __restrict__ in,   // t2 (hi,lo) [z][H][W][64]
    const __half* __restrict__ wf,   // [u][2][4][2][32][4]
    const float* __restrict__ b3, float* __restrict__ out,
    int H, int W, int nu, int interleave)
{
    extern __shared__ char cs[];
    __half* s_ah = (__half*)cs;               // [512*36]
    __half* s_al = (__half*)(cs + C3_AL_OFF); // [512*36]
    float*  s_d  = (float*)cs;                // alias: [512*34]
    __half* s_wf = (__half*)(cs + C3_WF_OFF); // 2048 halves

    int z = blockIdx.z;
    int u = z % nu;
    int b = z / nu;
    int tid = threadIdx.x;
    int warp = tid >> 5;
    int lane = tid & 31;
    int g = lane >> 2, t = lane & 3;
    int x0 = blockIdx.x * 16, y0 = blockIdx.y * 16;
    const __half* inz = in + (size_t)z * H * W * 64;

    ((uint4*)s_wf)[tid] = ((const uint4*)(wf + (size_t)u * 2048))[tid];

    // stage tile: 512 sites x 8 chunks of 4 ic (hi,lo interleaved -> split)
    for (int i = tid; i < 4096; i += 256) {
        int site = i >> 3, k = i & 7;
        uint4 v = make_uint4(0, 0, 0, 0);
        if (site < 400) {
            int sy = site / 20, sx = site - sy * 20;
            int gy = y0 + sy - 2, gx = x0 + sx - 2;
            if (gy >= 0 && gy < H && gx >= 0 && gx < W)
                v = *(const uint4*)(inz + ((size_t)gy * W + gx) * 64 + k * 8);
        }
        unsigned h01 = __byte_perm(v.x, v.y, 0x5410);
        unsigned l01 = __byte_perm(v.x, v.y, 0x7632);
        unsigned h23 = __byte_perm(v.z, v.w, 0x5410);
        unsigned l23 = __byte_perm(v.z, v.w, 0x7632);
        int off = site * 36 + k * 4;
        *(uint2*)&s_ah[off] = make_uint2(h01, h23);
        *(uint2*)&s_al[off] = make_uint2(l01, l23);
    }
    __syncthreads();

    uint2 bh[4][2], bl[4][2];
#pragma unroll
    for (int nt = 0; nt < 4; nt++)
#pragma unroll
        for (int ks = 0; ks < 2; ks++) {
            bh[nt][ks] = ((const uint2*)s_wf)[(nt * 2 + ks) * 32 + lane];
            bl[nt][ks] = ((const uint2*)s_wf)[((4 + nt) * 2 + ks) * 32 + lane];
        }

    float c[4][4][4];
#pragma unroll
    for (int mt = 0; mt < 4; mt++)
#pragma unroll
        for (int nt = 0; nt < 4; nt++)
#pragma unroll
            for (int q = 0; q < 4; q++) c[mt][nt][q] = 0.f;

#pragma unroll
    for (int mt = 0; mt < 4; mt++) {
        int m0 = (warp * 4 + mt) * 16;
#pragma unroll
        for (int ks = 0; ks < 2; ks++) {
            int ko = ks * 16 + 2 * t;
            uint4 ah, al;
            ah.x = *(const unsigned*)&s_ah[(m0 + g) * 36 + ko];
            ah.y = *(const unsigned*)&s_ah[(m0 + g + 8) * 36 + ko];
            ah.z = *(const unsigned*)&s_ah[(m0 + g) * 36 + ko + 8];
            ah.w = *(const unsigned*)&s_ah[(m0 + g + 8) * 36 + ko + 8];
            al.x = *(const unsigned*)&s_al[(m0 + g) * 36 + ko];
            al.y = *(const unsigned*)&s_al[(m0 + g + 8) * 36 + ko];
            al.z = *(const unsigned*)&s_al[(m0 + g) * 36 + ko + 8];
            al.w = *(const unsigned*)&s_al[(m0 + g + 8) * 36 + ko + 8];
#pragma unroll
            for (int nt = 0; nt < 4; nt++) {
                mma_f16(c[mt][nt], ah, bh[nt][ks].x, bh[nt][ks].y);
                mma_f16(c[mt][nt], al, bh[nt][ks].x, bh[nt][ks].y);
                mma_f16(c[mt][nt], ah, bl[nt][ks].x, bl[nt][ks].y);
            }
        }
    }
    __syncthreads();   // all A reads done before D aliases over s_ah/s_al

#pragma unroll
    for (int mt = 0; mt < 4; mt++) {
        int m0 = (warp * 4 + mt) * 16;
#pragma unroll
        for (int nt = 0; nt < 4; nt++) {
            int col = nt * 8 + 2 * t;
            *(float2*)&s_d[(m0 + g) * 34 + col] =
                make_float2(c[mt][nt][0], c[mt][nt][1]);
            *(float2*)&s_d[(m0 + g + 8) * 34 + col] =
                make_float2(c[mt][nt][2], c[mt][nt][3]);
        }
    }
    __syncthreads();

    int ty = tid >> 4, tx = tid & 15;
    float acc = b3[u];
#pragma unroll
    for (int dy = 0; dy < 5; dy++)
#pragma unroll
        for (int dx = 0; dx < 5; dx++)
            acc += s_d[((ty + dy) * 20 + tx + dx) * 34 + dy * 5 + dx];

    int y = y0 + ty, x = x0 + tx;
    if (interleave) {
        int uy = u >> 1, ux = u & 1;
        out[(size_t)b * 4 * H * W + (size_t)(2 * y + uy) * (2 * W) + 2 * x + ux] = acc;
    } else {
        out[(size_t)b * H * W + (size_t)y * W + x] = acc;
    }
}

// ---------------------------------------------------------------------------
// msf_in = up8(x2) + up4(x4) + up2(x8) + x16  (bilinear half-pixel, clamp)
// ---------------------------------------------------------------------------
__device__ __forceinline__ float bilin(const float* __restrict__ p, int N,
                                       float inv_s, int y, int x) {
    float sy = (y + 0.5f) * inv_s - 0.5f;
    float sx = (x + 0.5f) * inv_s - 0.5f;
    float fy0 = floorf(sy), fx0 = floorf(sx);
    float fy = sy - fy0, fx = sx - fx0;
    int y0 = (int)fy0, x0 = (int)fx0;
    int y0c = min(max(y0, 0), N - 1);
    int y1c = min(max(y0 + 1, 0), N - 1);
    int x0c = min(max(x0, 0), N - 1);
    int x1c = min(max(x0 + 1, 0), N - 1);
    float v00 = p[(size_t)y0c * N + x0c];
    float v01 = p[(size_t)y0c * N + x1c];
    float v10 = p[(size_t)y1c * N + x0c];
    float v11 = p[(size_t)y1c * N + x1c];
    return (1.f - fy) * ((1.f - fx) * v00 + fx * v01) +
           fy * ((1.f - fx) * v10 + fx * v11);
}

__global__ void msf_in_kernel(const float* __restrict__ x2,
                              const float* __restrict__ x4,
                              const float* __restrict__ x8,
                              const float* __restrict__ x16,
                              float* __restrict__ out) {
    int idx = blockIdx.x * 256 + threadIdx.x;
    if (idx >= 2 * 1024 * 1024) return;
    int b = idx >> 20;
    int r = idx & 0xFFFFF;
    int y = r >> 10, x = r & 1023;
    float v = x16[idx];
    v += bilin(x2 + (size_t)b * 128 * 128, 128, 0.125f, y, x);
    v += bilin(x4 + (size_t)b * 256 * 256, 256, 0.25f, y, x);
    v += bilin(x8 + (size_t)b * 512 * 512, 512, 0.5f, y, x);
    out[idx] = v;
}

// ---------------------------------------------------------------------------
// Host orchestration
// ---------------------------------------------------------------------------
extern "C" void kernel_launch(void* const* d_in, const int* in_sizes, int n_in,
                              void* d_out, int out_size) {
    const float* image = (const float*)d_in[0];
    const float* w1 = (const float*)d_in[1];
    const float* b1 = (const float*)d_in[2];
    const float* w2 = (const float*)d_in[3];
    const float* b2 = (const float*)d_in[4];
    const float* w3 = (const float*)d_in[5];
    const float* b3 = (const float*)d_in[6];
    float* out = (float*)d_out;

    __half *t1h, *t2hl, *w1h, *w2h, *w3f;
    float *msf;
    cudaGetSymbolAddress((void**)&t1h, g_t1h);
    cudaGetSymbolAddress((void**)&t2hl, g_t2hl);
    cudaGetSymbolAddress((void**)&msf, g_msf);
    cudaGetSymbolAddress((void**)&w1h, g_w1h);
    cudaGetSymbolAddress((void**)&w2h, g_w2h);
    cudaGetSymbolAddress((void**)&w3f, g_w3f);

    static bool attr_done = false;
    if (!attr_done) {
        cudaFuncSetAttribute(conv2_mma_kernel,
                             cudaFuncAttributeMaxDynamicSharedMemorySize, 76800);
        cudaFuncSetAttribute(conv3_mma_kernel,
                             cudaFuncAttributeMaxDynamicSharedMemorySize, C3_SMEM);
        attr_done = true;
    }

    prep_weights_kernel<<<850, 256>>>(w1, w2, w3);

    float* ox2 = out + 0;
    float* ox4 = out + 32768;
    float* ox8 = out + 163840;
    float* ox16 = out + 688128;
    float* omsf = out + 2785280;

    auto run_stage = [&](const float* inp, int H, int W, int ubase,
                         float* outp, int nu, int il) {
        dim3 g1(W / 16, H / 16, 2 * nu);
        conv1_mma_kernel<<<g1, 256>>>(inp, w1h + (size_t)ubase * 6144,
                                      b1 + (size_t)ubase * 64, t1h, H, W, nu);
        conv2_mma_kernel<<<g1, 256, 76800>>>(
            t1h, w2h + (size_t)ubase * 4 * 12800,
            b2 + (size_t)ubase * 32, t2hl, H, W, nu);
        conv3_mma_kernel<<<g1, 256, C3_SMEM>>>(
            t2hl, w3f + (size_t)ubase * 2048,
            b3 + ubase, outp, H, W, nu, il);
    };

    run_stage(image, 64, 64, 0, ox2, 4, 1);
    run_stage(ox2, 128, 128, 4, ox4, 4, 1);
    run_stage(ox4, 256, 256, 8, ox8, 4, 1);
    run_stage(ox8, 512, 512, 12, ox16, 4, 1);

    msf_in_kernel<<<(2 * 1024 * 1024) / 256, 256>>>(ox2, ox4, ox8, ox16, msf);

    run_stage(msf, 1024, 1024, 16, omsf, 1, 0);
}

// round 8
// speedup vs baseline: 1.6897x; 1.0828x over previous
#include <cuda_runtime.h>
#include <cuda_fp16.h>
#include <cstdint>

// ---------------------------------------------------------------------------
// DSDMSR multi-scale SRCNN cascade (sm_100 / compute_100 legacy mma path).
// conv1 (9x9,1->64): fp16 mma, split hi/lo activations; MSF input fused.
// conv2 (5x5,64->32): fp16 mma m16n8k16, cp.async double-buffered.
// conv3 (5x5,32->1): site-GEMM, 3-pass compensated + fp32 tap-sum.
// ---------------------------------------------------------------------------

__device__ __half g_t1h[134217728];          // conv1 out, [z][H][W][64] fp16
__device__ __half g_t2hl[134217728];         // conv2 out, [z][H][W][32*(hi,lo)]
__device__ __half g_w1h[17 * 6 * 8 * 32 * 4];      // conv1 w frag-major
__device__ __half g_w2h[17 * 4 * 25 * 2 * 32 * 8]; // conv2 w frag-major
__device__ __half g_w3f[17 * 2048];                // conv3 w frag-major (hi,lo)

__device__ __forceinline__ unsigned pkh(__half a, __half b) {
    __half2 p = __halves2half2(a, b);
    return *(unsigned*)&p;
}
__device__ __forceinline__ void mma_f16(float c[4], const uint4& a,
                                        unsigned b0, unsigned b1) {
    asm volatile(
        "mma.sync.aligned.m16n8k16.row.col.f32.f16.f16.f32 "
        "{%0,%1,%2,%3}, {%4,%5,%6,%7}, {%8,%9}, {%0,%1,%2,%3};"
        : "+f"(c[0]), "+f"(c[1]), "+f"(c[2]), "+f"(c[3])
        : "r"(a.x), "r"(a.y), "r"(a.z), "r"(a.w), "r"(b0), "r"(b1));
}
__device__ __forceinline__ void st_hl(__half* p, float v) {
    __half h = __float2half_rn(v);
    __half l = __float2half_rn(v - __half2float(h));
    *(__half2*)p = __halves2half2(h, l);
}
__device__ __forceinline__ uint32_t smem_u32(const void* p) {
    uint32_t a;
    asm("{ .reg .u64 t; cvta.to.shared.u64 t, %1; cvt.u32.u64 %0, t; }"
        : "=r"(a) : "l"(p));
    return a;
}
__device__ __forceinline__ void cpa16(uint32_t s, const void* g, bool pred) {
    int sz = pred ? 16 : 0;
    asm volatile("cp.async.cg.shared.global [%0], [%1], 16, %2;"
                 :: "r"(s), "l"(g), "r"(sz) : "memory");
}
#define CP_COMMIT() asm volatile("cp.async.commit_group;" ::: "memory")
#define CP_WAIT(n)  asm volatile("cp.async.wait_group %0;" :: "n"(n) : "memory")

// ---------------------------------------------------------------------------
// Weight prep: w1 frag-major, w2 frag-major, w3 frag-major hi/lo.
// ---------------------------------------------------------------------------
__global__ void prep_weights_kernel(const float* __restrict__ w1,
                                    const float* __restrict__ w2,
                                    const float* __restrict__ w3) {
    int idx = blockIdx.x * 256 + threadIdx.x;
    if (idx < 17 * 6 * 8 * 32) {
        int lane = idx & 31;
        int r = idx >> 5;
        int nt = r & 7; r >>= 3;
        int kc = r % 6;
        int u = r / 6;
        int g = lane >> 2, t = lane & 3;
        int oc = nt * 8 + g;
        int kt[4] = {kc * 16 + 2 * t, kc * 16 + 2 * t + 1,
                     kc * 16 + 2 * t + 8, kc * 16 + 2 * t + 9};
        __half* dst = g_w1h + (size_t)idx * 4;
#pragma unroll
        for (int q = 0; q < 4; q++)
            dst[q] = (kt[q] < 81)
                ? __float2half_rn(w1[((size_t)u * 64 + oc) * 81 + kt[q]])
                : __half(0.f);
    }
    if (idx < 17 * 4 * 25 * 2 * 32) {
        int l = idx & 31;
        int m = (idx >> 5) & 1;
        int rest = idx >> 6;
        int tap = rest % 25;
        int rest2 = rest / 25;
        int ch = rest2 & 3;
        int u = rest2 >> 2;
        int g = l >> 2, t = l & 3;
        int oc0 = m * 16 + g;
        int ic0 = ch * 16;
        __half* dst = g_w2h + (size_t)idx * 8;
#pragma unroll
        for (int q = 0; q < 8; q++) {
            int oc = oc0 + ((q >> 1) & 1) * 8;
            int ic = ic0 + 2 * t + (q & 1) + (q >> 2) * 8;
            dst[q] = __float2half_rn(w2[((size_t)(u * 32 + oc) * 64 + ic) * 25 + tap]);
        }
    }
    if (idx < 17 * 2 * 4 * 2 * 32) {
        int lane = idx & 31;
        int r = idx >> 5;
        int ks = r & 1; r >>= 1;
        int nt = r & 3; r >>= 2;
        int hl = r & 1; r >>= 1;
        int u = r;
        int g = lane >> 2, t = lane & 3;
        int tap = nt * 8 + g;
        __half* dst = g_w3f + (size_t)idx * 4;
#pragma unroll
        for (int q = 0; q < 4; q++) {
            int kq = ks * 16 + 2 * t + (q & 1) + (q >> 1) * 8;
            float v = (tap < 25) ? w3[(size_t)u * 800 + kq * 25 + tap] : 0.f;
            __half h = __float2half_rn(v);
            dst[q] = (hl == 0) ? h : __float2half_rn(v - __half2float(h));
        }
    }
}

// ---------------------------------------------------------------------------
// bilinear (half-pixel centers, clamp) — used by fused MSF input path.
// ---------------------------------------------------------------------------
__device__ __forceinline__ float bilin(const float* __restrict__ p, int N,
                                       float inv_s, int y, int x) {
    float sy = (y + 0.5f) * inv_s - 0.5f;
    float sx = (x + 0.5f) * inv_s - 0.5f;
    float fy0 = floorf(sy), fx0 = floorf(sx);
    float fy = sy - fy0, fx = sx - fx0;
    int y0 = (int)fy0, x0 = (int)fx0;
    int y0c = min(max(y0, 0), N - 1);
    int y1c = min(max(y0 + 1, 0), N - 1);
    int x0c = min(max(x0, 0), N - 1);
    int x1c = min(max(x0 + 1, 0), N - 1);
    float v00 = p[(size_t)y0c * N + x0c];
    float v01 = p[(size_t)y0c * N + x1c];
    float v10 = p[(size_t)y1c * N + x0c];
    float v11 = p[(size_t)y1c * N + x1c];
    return (1.f - fy) * ((1.f - fx) * v00 + fx * v01) +
           fy * ((1.f - fx) * v10 + fx * v11);
}

// ---------------------------------------------------------------------------
// conv1: 9x9, 1->64, ReLU via fp16 mma, split activations.
// msf_mode: input = x16 + up8(x2) + up4(x4) + up2(x8) computed inline.
// ---------------------------------------------------------------------------
__global__ __launch_bounds__(256) void conv1_mma_kernel(
    const float* __restrict__ in, const __half* __restrict__ wt,
    const float* __restrict__ bias, __half* __restrict__ out,
    int H, int W, int nu, int msf_mode,
    const float* __restrict__ mx2, const float* __restrict__ mx4,
    const float* __restrict__ mx8)
{
    __shared__ __half s_h[24 * 24];
    __shared__ __half s_l[24 * 24];
    __shared__ __half s_w[6144];
    __shared__ float s_b[64];

    int z = blockIdx.z;
    int u = z % nu;
    int b = z / nu;
    int tid = threadIdx.x;
    int warp = tid >> 5;
    int lane = tid & 31;
    int x0 = blockIdx.x * 16, y0 = blockIdx.y * 16;
    const float* inb = in + (size_t)b * H * W;
    const __half* wu = wt + (size_t)u * 6144;

    for (int i = tid; i < 576; i += 256) {
        int iy = i / 24, ix = i - iy * 24;
        int gy = y0 + iy - 4, gx = x0 + ix - 4;
        float v = 0.f;
        if (gy >= 0 && gy < H && gx >= 0 && gx < W) {
            if (!msf_mode) {
                v = inb[(size_t)gy * W + gx];
            } else {
                v = inb[(size_t)gy * W + gx]                           // x16
                  + bilin(mx2 + (size_t)b * 16384, 128, 0.125f, gy, gx)
                  + bilin(mx4 + (size_t)b * 65536, 256, 0.25f, gy, gx)
                  + bilin(mx8 + (size_t)b * 262144, 512, 0.5f, gy, gx);
            }
        }
        __half h = __float2half_rn(v);
        s_h[i] = h;
        s_l[i] = __float2half_rn(v - __half2float(h));
    }
    for (int i = tid; i < 768; i += 256)
        ((uint4*)s_w)[i] = ((const uint4*)wu)[i];
    if (tid < 64) s_b[tid] = bias[u * 64 + tid];
    __syncthreads();

    int g = lane >> 2, t = lane & 3;
    int r0 = warp * 2;

    float c[2][8][4];
#pragma unroll
    for (int m = 0; m < 2; m++)
#pragma unroll
        for (int nt = 0; nt < 8; nt++)
#pragma unroll
            for (int q = 0; q < 4; q++) c[m][nt][q] = 0.f;

#pragma unroll
    for (int kc = 0; kc < 6; kc++) {
        uint2 breg[8];
#pragma unroll
        for (int nt = 0; nt < 8; nt++)
            breg[nt] = *(const uint2*)&s_w[((kc * 8 + nt) * 32 + lane) * 4];

        int o[4];
#pragma unroll
        for (int q = 0; q < 4; q++) {
            int tap = kc * 16 + 2 * t + (q & 1) + (q >> 1) * 8;
            tap = min(tap, 80);
            int dy = tap / 9, dx = tap - 9 * dy;
            o[q] = dy * 24 + dx;
        }

#pragma unroll
        for (int mrow = 0; mrow < 2; mrow++) {
            int base = (r0 + mrow) * 24;
            const __half* sh = s_h + base;
            const __half* sl = s_l + base;
            uint4 ah, al;
            ah.x = pkh(sh[o[0] + g],     sh[o[1] + g]);
            ah.y = pkh(sh[o[0] + g + 8], sh[o[1] + g + 8]);
            ah.z = pkh(sh[o[2] + g],     sh[o[3] + g]);
            ah.w = pkh(sh[o[2] + g + 8], sh[o[3] + g + 8]);
            al.x = pkh(sl[o[0] + g],     sl[o[1] + g]);
            al.y = pkh(sl[o[0] + g + 8], sl[o[1] + g + 8]);
            al.z = pkh(sl[o[2] + g],     sl[o[3] + g]);
            al.w = pkh(sl[o[2] + g + 8], sl[o[3] + g + 8]);
#pragma unroll
            for (int nt = 0; nt < 8; nt++) {
                mma_f16(c[mrow][nt], ah, breg[nt].x, breg[nt].y);
                mma_f16(c[mrow][nt], al, breg[nt].x, breg[nt].y);
            }
        }
    }

#pragma unroll
    for (int mrow = 0; mrow < 2; mrow++) {
        int y = y0 + r0 + mrow;
#pragma unroll
        for (int nt = 0; nt < 8; nt++) {
            int oc0 = nt * 8 + 2 * t;
            float bv0 = s_b[oc0], bv1 = s_b[oc0 + 1];
            __half2 v0 = __halves2half2(
                __float2half_rn(fmaxf(c[mrow][nt][0] + bv0, 0.f)),
                __float2half_rn(fmaxf(c[mrow][nt][1] + bv1, 0.f)));
            __half2 v1 = __halves2half2(
                __float2half_rn(fmaxf(c[mrow][nt][2] + bv0, 0.f)),
                __float2half_rn(fmaxf(c[mrow][nt][3] + bv1, 0.f)));
            *(__half2*)(out + (((size_t)z * H + y) * W + x0 + g) * 64 + oc0) = v0;
            *(__half2*)(out + (((size_t)z * H + y) * W + x0 + g + 8) * 64 + oc0) = v1;
        }
    }
}

// ---------------------------------------------------------------------------
// conv2: 5x5, 64->32, ReLU via fp16 mma, cp.async double-buffered.
// Output: interleaved (hi,lo) fp16 pairs, [z][H][W][oc*2].
// ---------------------------------------------------------------------------
__global__ __launch_bounds__(256) void conv2_mma_kernel(
    const __half* __restrict__ in,    // [z][H][W][64] fp16
    const __half* __restrict__ wt,    // [nu][4][25][2][32][8] frag-major
    const float* __restrict__ bias,   // [nu][32]
    __half* __restrict__ out,         // [z][H][W][64] (hi,lo interleaved)
    int H, int W, int nu)
{
    extern __shared__ __half s2[];
    __half* s_raw = s2;            // [2][400*16]
    __half* s_wt  = s2 + 12800;    // [2][12800]

    int z = blockIdx.z;
    int u = z % nu;
    int tid = threadIdx.x;
    int warp = tid >> 5;
    int lane = tid & 31;
    int x0 = blockIdx.x * 16, y0 = blockIdx.y * 16;
    const __half* inz = in + (size_t)z * H * W * 64;
    const __half* wu = wt + (size_t)u * 4 * 12800;

    int g = lane >> 2, t = lane & 3;
    int r0 = warp * 2;

    int bbase[4];
#pragma unroll
    for (int j = 0; j < 4; j++)
        bbase[j] = ((r0 + (j >> 1)) * 20 + (j & 1) * 8 + g) * 16 + 2 * t;

    float c[2][4][4];
#pragma unroll
    for (int m = 0; m < 2; m++)
#pragma unroll
        for (int j = 0; j < 4; j++)
#pragma unroll
            for (int q = 0; q < 4; q++) c[m][j][q] = 0.f;

    uint32_t raw_sm0 = smem_u32(s_raw);
    uint32_t wt_sm0 = smem_u32(s_wt);

    auto issue_chunk = [&](int ch) {
        uint32_t raw = raw_sm0 + (ch & 1) * 12800;   // bytes
        uint32_t ww  = wt_sm0 + (ch & 1) * 25600;
#pragma unroll
        for (int l = 0; l < 4; l++) {
            int i = tid + l * 256;
            if (i < 800) {
                int site = i >> 1, part = i & 1;
                int py = site / 20, px = site - py * 20;
                int gy = y0 + py - 2, gx = x0 + px - 2;
                bool ok = (gy >= 0 && gy < H && gx >= 0 && gx < W);
                const void* src = ok
                    ? (const void*)&inz[((size_t)gy * W + gx) * 64 + ch * 16 + part * 8]
                    : (const void*)inz;
                cpa16(raw + site * 32 + part * 16, src, ok);
            }
        }
        const uint4* wsrc = (const uint4*)(wu + (size_t)ch * 12800);
#pragma unroll
        for (int l = 0; l < 7; l++) {
            int i = tid + l * 256;
            if (i < 1600) cpa16(ww + i * 16, wsrc + i, true);
        }
        CP_COMMIT();
    };

    issue_chunk(0);

#pragma unroll
    for (int ch = 0; ch < 4; ch++) {
        if (ch > 0) __syncthreads();        // all warps done with buf (ch+1)&1
        if (ch < 3) issue_chunk(ch + 1);
        if (ch < 3) { CP_WAIT(1); } else { CP_WAIT(0); }
        __syncthreads();

        const __half* raw = s_raw + (ch & 1) * 6400;
        const __half* sw  = s_wt  + (ch & 1) * 12800;

#pragma unroll
        for (int dy = 0; dy < 5; dy++) {
#pragma unroll
            for (int dx = 0; dx < 5; dx++) {
                int tap = dy * 5 + dx;
                int toff = (dy * 20 + dx) * 16;
                uint4 a0 = *(const uint4*)&sw[(size_t)(tap * 2 + 0) * 256 + lane * 8];
                uint4 a1 = *(const uint4*)&sw[(size_t)(tap * 2 + 1) * 256 + lane * 8];
#pragma unroll
                for (int j = 0; j < 4; j++) {
                    unsigned b0 = *(const unsigned*)&raw[bbase[j] + toff];
                    unsigned b1 = *(const unsigned*)&raw[bbase[j] + toff + 8];
                    mma_f16(c[0][j], a0, b0, b1);
                    mma_f16(c[1][j], a1, b0, b1);
                }
            }
        }
    }

#pragma unroll
    for (int m = 0; m < 2; m++) {
        int oc0 = m * 16 + g;
        float bv0 = bias[u * 32 + oc0];
        float bv1 = bias[u * 32 + oc0 + 8];
#pragma unroll
        for (int j = 0; j < 4; j++) {
            int y = y0 + r0 + (j >> 1);
            int xb = x0 + (j & 1) * 8 + 2 * t;
            __half* base = out + (((size_t)z * H + y) * W + xb) * 64;
            st_hl(base + oc0 * 2,            fmaxf(c[m][j][0] + bv0, 0.f));
            st_hl(base + 64 + oc0 * 2,       fmaxf(c[m][j][1] + bv0, 0.f));
            st_hl(base + (oc0 + 8) * 2,      fmaxf(c[m][j][2] + bv1, 0.f));
            st_hl(base + 64 + (oc0 + 8) * 2, fmaxf(c[m][j][3] + bv1, 0.f));
        }
    }
}

// ---------------------------------------------------------------------------
// conv3: 5x5, 32->1 via site-GEMM D[site,tap] then fp32 tap-sum.
// 3 compensated passes: Ah*Wh + Al*Wh + Ah*Wl.  16x16 out tile, 256 thr.
// ---------------------------------------------------------------------------
#define C3_AL_OFF  36864
#define C3_WF_OFF  73728
#define C3_SMEM    77824

__global__ __launch_bounds__(256) void conv3_mma_kernel(
    const __half* __restrict__ in,   // t2 (hi,lo) [z][H][W][64]
    const __half* __restrict__ wf,   // [u][2][4][2][32][4]
    const float* __restrict__ b3, float* __restrict__ out,
    int H, int W, int nu, int interleave)
{
    extern __shared__ char cs[];
    __half* s_ah = (__half*)cs;               // [512*36]
    __half* s_al = (__half*)(cs + C3_AL_OFF); // [512*36]
    float*  s_d  = (float*)cs;                // alias: [512*34]
    __half* s_wf = (__half*)(cs + C3_WF_OFF); // 2048 halves

    int z = blockIdx.z;
    int u = z % nu;
    int b = z / nu;
    int tid = threadIdx.x;
    int warp = tid >> 5;
    int lane = tid & 31;
    int g = lane >> 2, t = lane & 3;
    int x0 = blockIdx.x * 16, y0 = blockIdx.y * 16;
    const __half* inz = in + (size_t)z * H * W * 64;

    ((uint4*)s_wf)[tid] = ((const uint4*)(wf + (size_t)u * 2048))[tid];

    for (int i = tid; i < 4096; i += 256) {
        int site = i >> 3, k = i & 7;
        uint4 v = make_uint4(0, 0, 0, 0);
        if (site < 400) {
            int sy = site / 20, sx = site - sy * 20;
            int gy = y0 + sy - 2, gx = x0 + sx - 2;
            if (gy >= 0 && gy < H && gx >= 0 && gx < W)
                v = *(const uint4*)(inz + ((size_t)gy * W + gx) * 64 + k * 8);
        }
        unsigned h01 = __byte_perm(v.x, v.y, 0x5410);
        unsigned l01 = __byte_perm(v.x, v.y, 0x7632);
        unsigned h23 = __byte_perm(v.z, v.w, 0x5410);
        unsigned l23 = __byte_perm(v.z, v.w, 0x7632);
        int off = site * 36 + k * 4;
        *(uint2*)&s_ah[off] = make_uint2(h01, h23);
        *(uint2*)&s_al[off] = make_uint2(l01, l23);
    }
    __syncthreads();

    uint2 bh[4][2], bl[4][2];
#pragma unroll
    for (int nt = 0; nt < 4; nt++)
#pragma unroll
        for (int ks = 0; ks < 2; ks++) {
            bh[nt][ks] = ((const uint2*)s_wf)[(nt * 2 + ks) * 32 + lane];
            bl[nt][ks] = ((const uint2*)s_wf)[((4 + nt) * 2 + ks) * 32 + lane];
        }

    float c[4][4][4];
#pragma unroll
    for (int mt = 0; mt < 4; mt++)
#pragma unroll
        for (int nt = 0; nt < 4; nt++)
#pragma unroll
            for (int q = 0; q < 4; q++) c[mt][nt][q] = 0.f;

#pragma unroll
    for (int mt = 0; mt < 4; mt++) {
        int m0 = (warp * 4 + mt) * 16;
#pragma unroll
        for (int ks = 0; ks < 2; ks++) {
            int ko = ks * 16 + 2 * t;
            uint4 ah, al;
            ah.x = *(const unsigned*)&s_ah[(m0 + g) * 36 + ko];
            ah.y = *(const unsigned*)&s_ah[(m0 + g + 8) * 36 + ko];
            ah.z = *(const unsigned*)&s_ah[(m0 + g) * 36 + ko + 8];
            ah.w = *(const unsigned*)&s_ah[(m0 + g + 8) * 36 + ko + 8];
            al.x = *(const unsigned*)&s_al[(m0 + g) * 36 + ko];
            al.y = *(const unsigned*)&s_al[(m0 + g + 8) * 36 + ko];
            al.z = *(const unsigned*)&s_al[(m0 + g) * 36 + ko + 8];
            al.w = *(const unsigned*)&s_al[(m0 + g + 8) * 36 + ko + 8];
#pragma unroll
            for (int nt = 0; nt < 4; nt++) {
                mma_f16(c[mt][nt], ah, bh[nt][ks].x, bh[nt][ks].y);
                mma_f16(c[mt][nt], al, bh[nt][ks].x, bh[nt][ks].y);
                mma_f16(c[mt][nt], ah, bl[nt][ks].x, bl[nt][ks].y);
            }
        }
    }
    __syncthreads();

#pragma unroll
    for (int mt = 0; mt < 4; mt++) {
        int m0 = (warp * 4 + mt) * 16;
#pragma unroll
        for (int nt = 0; nt < 4; nt++) {
            int col = nt * 8 + 2 * t;
            *(float2*)&s_d[(m0 + g) * 34 + col] =
                make_float2(c[mt][nt][0], c[mt][nt][1]);
            *(float2*)&s_d[(m0 + g + 8) * 34 + col] =
                make_float2(c[mt][nt][2], c[mt][nt][3]);
        }
    }
    __syncthreads();

    int ty = tid >> 4, tx = tid & 15;
    float acc = b3[u];
#pragma unroll
    for (int dy = 0; dy < 5; dy++)
#pragma unroll
        for (int dx = 0; dx < 5; dx++)
            acc += s_d[((ty + dy) * 20 + tx + dx) * 34 + dy * 5 + dx];

    int y = y0 + ty, x = x0 + tx;
    if (interleave) {
        int uy = u >> 1, ux = u & 1;
        out[(size_t)b * 4 * H * W + (size_t)(2 * y + uy) * (2 * W) + 2 * x + ux] = acc;
    } else {
        out[(size_t)b * H * W + (size_t)y * W + x] = acc;
    }
}

// ---------------------------------------------------------------------------
// Host orchestration
// ---------------------------------------------------------------------------
extern "C" void kernel_launch(void* const* d_in, const int* in_sizes, int n_in,
                              void* d_out, int out_size) {
    const float* image = (const float*)d_in[0];
    const float* w1 = (const float*)d_in[1];
    const float* b1 = (const float*)d_in[2];
    const float* w2 = (const float*)d_in[3];
    const float* b2 = (const float*)d_in[4];
    const float* w3 = (const float*)d_in[5];
    const float* b3 = (const float*)d_in[6];
    float* out = (float*)d_out;

    __half *t1h, *t2hl, *w1h, *w2h, *w3f;
    cudaGetSymbolAddress((void**)&t1h, g_t1h);
    cudaGetSymbolAddress((void**)&t2hl, g_t2hl);
    cudaGetSymbolAddress((void**)&w1h, g_w1h);
    cudaGetSymbolAddress((void**)&w2h, g_w2h);
    cudaGetSymbolAddress((void**)&w3f, g_w3f);

    static bool attr_done = false;
    if (!attr_done) {
        cudaFuncSetAttribute(conv2_mma_kernel,
                             cudaFuncAttributeMaxDynamicSharedMemorySize, 76800);
        cudaFuncSetAttribute(conv3_mma_kernel,
                             cudaFuncAttributeMaxDynamicSharedMemorySize, C3_SMEM);
        attr_done = true;
    }

    prep_weights_kernel<<<850, 256>>>(w1, w2, w3);

    float* ox2 = out + 0;
    float* ox4 = out + 32768;
    float* ox8 = out + 163840;
    float* ox16 = out + 688128;
    float* omsf = out + 2785280;

    auto run_stage = [&](const float* inp, int H, int W, int ubase,
                         float* outp, int nu, int il, int msf_mode) {
        dim3 g1(W / 16, H / 16, 2 * nu);
        conv1_mma_kernel<<<g1, 256>>>(inp, w1h + (size_t)ubase * 6144,
                                      b1 + (size_t)ubase * 64, t1h, H, W, nu,
                                      msf_mode, ox2, ox4, ox8);
        conv2_mma_kernel<<<g1, 256, 76800>>>(
            t1h, w2h + (size_t)ubase * 4 * 12800,
            b2 + (size_t)ubase * 32, t2hl, H, W, nu);
        conv3_mma_kernel<<<g1, 256, C3_SMEM>>>(
            t2hl, w3f + (size_t)ubase * 2048,
            b3 + ubase, outp, H, W, nu, il);
    };

    run_stage(image, 64, 64, 0, ox2, 4, 1, 0);
    run_stage(ox2, 128, 128, 4, ox4, 4, 1, 0);
    run_stage(ox4, 256, 256, 8, ox8, 4, 1, 0);
    run_stage(ox8, 512, 512, 12, ox16, 4, 1, 0);
    // MSF stage: conv1 computes x16 + up8(x2)+up4(x4)+up2(x8) inline from ox16.
    run_stage(ox16, 1024, 1024, 16, omsf, 1, 0, 1);
}